// round 10
// baseline (speedup 1.0000x reference)
#include <cuda_runtime.h>
#include <cuda_bf16.h>
#include <float.h>
#include <math.h>
#include <cstdint>

#define NNODES 2048
#define DIM    512
#define HIDD   256
#define NHEAD  4
#define TOPK   6
#define MAXD   256
#define NCAND  384   // 16 block-cols * 4 warps * 6

// ================= scratch (device globals; per-branch where concurrent) =================
__device__ __align__(16) float g_Xn[NNODES * DIM];
__device__ __align__(16) float g_sq[2][NNODES];
__device__ __align__(16) float g_cand_v[2][NNODES * NCAND];
__device__ int g_cand_i[2][NNODES * NCAND];
__device__ __align__(16) __nv_bfloat16 g_Ap[2][NNODES * 3 * 1024];
__device__ __align__(16) __nv_bfloat16 g_Bp[2][NNODES * 3 * DIM];
__device__ __align__(16) __nv_bfloat16 g_Wp[2][1024 * 3 * 1024];
__device__ unsigned g_bits[2][NNODES * 64];
__device__ int   g_nbr[2][NNODES * MAXD];
__device__ int   g_cnt[2][NNODES];
__device__ __align__(16) float g_Wh[2][NNODES * NHEAD * HIDD];
__device__ __align__(16) float g_s1[2][NHEAD * NNODES];
__device__ __align__(16) float g_s2[2][NHEAD * NNODES];
__device__ __align__(16) float g_hidden[2][NNODES * NHEAD * HIDD];
__device__ __align__(16) float g_WhO[2][NNODES * HIDD];
__device__ __align__(16) float g_sO1[2][NNODES];
__device__ __align__(16) float g_sO2[2][NNODES];
__device__ __align__(16) float g_pair[NNODES * 2 * HIDD];
__device__ __align__(16) float g_m1[NNODES * 512];
__device__ __align__(16) float g_m2[NNODES * 256];
__device__ __align__(16) float g_m3[NNODES * 128];

// ================= small PTX helpers =================
__device__ __forceinline__ uint32_t smem_to_u32(const void* p) {
    uint32_t a;
    asm("{ .reg .u64 t; cvta.to.shared.u64 t, %1; cvt.u32.u64 %0, t; }" : "=r"(a) : "l"(p));
    return a;
}
__device__ __forceinline__ void cp_async16(uint32_t saddr, const void* gaddr) {
    asm volatile("cp.async.cg.shared.global [%0], [%1], 16;" :: "r"(saddr), "l"(gaddr));
}
__device__ __forceinline__ void cp_commit() { asm volatile("cp.async.commit_group;"); }
template <int N>
__device__ __forceinline__ void cp_wait() { asm volatile("cp.async.wait_group %0;" :: "n"(N)); }

__device__ __forceinline__ void ldmatrix_x4(uint32_t* r, uint32_t addr) {
    asm volatile("ldmatrix.sync.aligned.m8n8.x4.shared.b16 {%0,%1,%2,%3}, [%4];"
                 : "=r"(r[0]), "=r"(r[1]), "=r"(r[2]), "=r"(r[3]) : "r"(addr));
}
__device__ __forceinline__ void ldmatrix_x2(uint32_t* r, uint32_t addr) {
    asm volatile("ldmatrix.sync.aligned.m8n8.x2.shared.b16 {%0,%1}, [%2];"
                 : "=r"(r[0]), "=r"(r[1]) : "r"(addr));
}
__device__ __forceinline__ void mma16816(float* c, const uint32_t* a, const uint32_t* b) {
    asm volatile(
        "mma.sync.aligned.m16n8k16.row.col.f32.bf16.bf16.f32 "
        "{%0,%1,%2,%3}, {%4,%5,%6,%7}, {%8,%9}, {%0,%1,%2,%3};"
        : "+f"(c[0]), "+f"(c[1]), "+f"(c[2]), "+f"(c[3])
        : "r"(a[0]), "r"(a[1]), "r"(a[2]), "r"(a[3]), "r"(b[0]), "r"(b[1]));
}

__device__ __forceinline__ bool tk_better(float v1, int i1, float v2, int i2) {
    return (v1 > v2) || (v1 == v2 && i1 < i2);
}

// ================= row norms =================
__global__ void rowstat_kernel(const float* __restrict__ X, float* __restrict__ Xn,
                               float* __restrict__ sq) {
    int i = blockIdx.x;
    int t = threadIdx.x;  // 256
    float s = 0.f;
    for (int d = t; d < DIM; d += 256) { float v = X[(size_t)i * DIM + d]; s += v * v; }
    __shared__ float sh[256];
    sh[t] = s; __syncthreads();
    for (int k = 128; k; k >>= 1) { if (t < k) sh[t] += sh[t + k]; __syncthreads(); }
    float tot = sh[0];
    if (t == 0) sq[i] = tot;
    if (Xn) {
        float inv = 1.0f / sqrtf(tot);
        for (int d = t; d < DIM; d += 256) Xn[(size_t)i * DIM + d] = X[(size_t)i * DIM + d] * inv;
    }
}

// ================= packing =================
// A pattern: [hi | hi | lo] ; B pattern: [hi | lo | hi]
__global__ void pack3_kernel(const float* __restrict__ src, __nv_bfloat16* __restrict__ dst,
                             int K, int total, int pat) {
    int idx = blockIdx.x * blockDim.x + threadIdx.x;
    if (idx >= total) return;
    int row = idx / K, col = idx % K;
    float x = src[idx];
    __nv_bfloat16 hi = __float2bfloat16(x);
    __nv_bfloat16 lo = __float2bfloat16(x - __bfloat162float(hi));
    size_t base = (size_t)row * 3 * K + col;
    dst[base] = hi;
    dst[base + K] = pat ? lo : hi;
    dst[base + 2 * K] = pat ? hi : lo;
}

__global__ void pack3AB_kernel(const float* __restrict__ src, __nv_bfloat16* __restrict__ dA,
                               __nv_bfloat16* __restrict__ dB, int K, int total) {
    int idx = blockIdx.x * blockDim.x + threadIdx.x;
    if (idx >= total) return;
    int row = idx / K, col = idx % K;
    float x = src[idx];
    __nv_bfloat16 hi = __float2bfloat16(x);
    __nv_bfloat16 lo = __float2bfloat16(x - __bfloat162float(hi));
    size_t base = (size_t)row * 3 * K + col;
    dA[base] = hi; dA[base + K] = hi; dA[base + 2 * K] = lo;
    dB[base] = hi; dB[base + K] = lo; dB[base + 2 * K] = hi;
}

__global__ void packWh3_kernel(const float* __restrict__ W, __nv_bfloat16* __restrict__ dst) {
    int idx = blockIdx.x * blockDim.x + threadIdx.x;
    if (idx >= NHEAD * HIDD * DIM) return;
    int n = idx / DIM, k = idx % DIM;
    int h = n / HIDD, hid = n % HIDD;
    float w = W[(size_t)h * DIM * HIDD + (size_t)k * HIDD + hid];
    __nv_bfloat16 hi = __float2bfloat16(w);
    __nv_bfloat16 lo = __float2bfloat16(w - __bfloat162float(hi));
    size_t base = (size_t)n * 3 * DIM + k;
    dst[base] = hi; dst[base + DIM] = lo; dst[base + 2 * DIM] = hi;
}

__global__ void packWgen3_kernel(const float* __restrict__ W, __nv_bfloat16* __restrict__ dst,
                                 int K, int N) {
    int idx = blockIdx.x * blockDim.x + threadIdx.x;
    if (idx >= N * K) return;
    int n = idx / K, k = idx % K;
    float w = W[(size_t)k * N + n];
    __nv_bfloat16 hi = __float2bfloat16(w);
    __nv_bfloat16 lo = __float2bfloat16(w - __bfloat162float(hi));
    size_t base = (size_t)n * 3 * K + k;
    dst[base] = hi; dst[base + K] = lo; dst[base + 2 * K] = hi;
}

// ================= mma.sync bf16 GEMM, 3-stage pipeline =================
// C[M,Nc] = A[M,K] @ B[Nc,K]^T ; 128x128 tile, BK=64, SW128 swizzle, 8 warps (2x4).
// DOTOPK: skip C write; per-row top-6 candidates within each warp's 32-col segment.
#define MMA_STAGES 3
#define MMA_SMEM_BYTES (MMA_STAGES * 32768)

template <bool DOTOPK>
__global__ void __launch_bounds__(256, 2)
mma_gemm_t(const __nv_bfloat16* __restrict__ A, const __nv_bfloat16* __restrict__ B,
           float* __restrict__ C, int Nc, int K, const float* __restrict__ bias, int relu,
           float* __restrict__ cv, int* __restrict__ ci, const float* __restrict__ sq,
           int mode) {
    extern __shared__ char sm[];
    const int tid = threadIdx.x;
    const int lane = tid & 31;
    const int warp = tid >> 5;
    const int wm = warp >> 2;   // 0..1
    const int wn = warp & 3;    // 0..3
    const int row0 = blockIdx.y * 128;
    const int col0 = blockIdx.x * 128;
    const uint32_t sbase = smem_to_u32(sm);

    const __nv_bfloat16* Aptr = A + (size_t)row0 * K;
    const __nv_bfloat16* Bptr = B + (size_t)col0 * K;

    float acc[4][4][4];
#pragma unroll
    for (int mt = 0; mt < 4; mt++)
#pragma unroll
        for (int nt = 0; nt < 4; nt++)
#pragma unroll
            for (int q = 0; q < 4; q++) acc[mt][nt][q] = 0.f;

    const int nch = K / 64;
    auto issue = [&](int c) {
        uint32_t base = sbase + (c % MMA_STAGES) * 32768;
        int koff = c * 64;
#pragma unroll
        for (int l = 0; l < 4; l++) {
            int idx = tid + l * 256;
            int r = idx >> 3;
            int jb = (idx & 7) * 16;
            unsigned off = r * 128 + jb;
            unsigned sw = off ^ ((off >> 3) & 0x70);
            cp_async16(base + sw, (const char*)(Aptr + (size_t)r * K + koff) + jb);
            cp_async16(base + 16384 + sw, (const char*)(Bptr + (size_t)r * K + koff) + jb);
        }
        cp_commit();
    };

    issue(0);
    issue(1);
    for (int c = 0; c < nch; c++) {
        cp_wait<1>();
        __syncthreads();
        if (c + 2 < nch) issue(c + 2); else cp_commit();
        uint32_t aBase = sbase + (c % MMA_STAGES) * 32768;
        uint32_t bBase = aBase + 16384;
#pragma unroll
        for (int ks = 0; ks < 4; ks++) {
            uint32_t af[4][4], bf[4][2];
#pragma unroll
            for (int mt = 0; mt < 4; mt++) {
                int r = wm * 64 + mt * 16 + (lane & 15);
                unsigned off = r * 128 + ks * 32 + (lane >> 4) * 16;
                unsigned sw = off ^ ((off >> 3) & 0x70);
                ldmatrix_x4(af[mt], aBase + sw);
            }
#pragma unroll
            for (int nt = 0; nt < 4; nt++) {
                int r = wn * 32 + nt * 8 + (lane & 7);
                unsigned off = r * 128 + ks * 32 + ((lane >> 3) & 1) * 16;
                unsigned sw = off ^ ((off >> 3) & 0x70);
                ldmatrix_x2(bf[nt], bBase + sw);
            }
#pragma unroll
            for (int mt = 0; mt < 4; mt++)
#pragma unroll
                for (int nt = 0; nt < 4; nt++)
                    mma16816(acc[mt][nt], af[mt], bf[nt]);
        }
        __syncthreads();
    }

    if (!DOTOPK) {
#pragma unroll
        for (int mt = 0; mt < 4; mt++) {
            int r0 = row0 + wm * 64 + mt * 16 + (lane >> 2);
#pragma unroll
            for (int nt = 0; nt < 4; nt++) {
                int cc = col0 + wn * 32 + nt * 8 + (lane & 3) * 2;
                float b0 = 0.f, b1 = 0.f;
                if (bias) { b0 = bias[cc]; b1 = bias[cc + 1]; }
                float v0 = acc[mt][nt][0] + b0, v1 = acc[mt][nt][1] + b1;
                float v2 = acc[mt][nt][2] + b0, v3 = acc[mt][nt][3] + b1;
                if (relu) {
                    v0 = fmaxf(v0, 0.f); v1 = fmaxf(v1, 0.f);
                    v2 = fmaxf(v2, 0.f); v3 = fmaxf(v3, 0.f);
                }
                *(float2*)(C + (size_t)r0 * Nc + cc) = make_float2(v0, v1);
                *(float2*)(C + (size_t)(r0 + 8) * Nc + cc) = make_float2(v2, v3);
            }
        }
    } else {
        // per-row top-6 candidates over this warp's 32-col segment.
        // 4-lane group (same lane>>2) holds one row's 32 cols (8 per lane).
#pragma unroll
        for (int mt = 0; mt < 4; mt++) {
#pragma unroll
            for (int half = 0; half < 2; half++) {
                int row = row0 + wm * 64 + mt * 16 + (lane >> 2) + half * 8;
                float bv[TOPK]; int bi[TOPK];
#pragma unroll
                for (int k = 0; k < TOPK; k++) { bv[k] = -FLT_MAX; bi[k] = 0x7fffffff; }
#pragma unroll
                for (int nt = 0; nt < 4; nt++) {
#pragma unroll
                    for (int q = 0; q < 2; q++) {
                        float v = acc[mt][nt][half * 2 + q];
                        int cidx = col0 + wn * 32 + nt * 8 + (lane & 3) * 2 + q;
                        float key = (mode == 0) ? (2.f * v - sq[cidx]) : v;
                        if (tk_better(key, cidx, bv[TOPK - 1], bi[TOPK - 1])) {
                            bv[TOPK - 1] = key; bi[TOPK - 1] = cidx;
#pragma unroll
                            for (int k = TOPK - 1; k > 0; k--) {
                                if (tk_better(bv[k], bi[k], bv[k - 1], bi[k - 1])) {
                                    float tv = bv[k]; bv[k] = bv[k - 1]; bv[k - 1] = tv;
                                    int ti = bi[k]; bi[k] = bi[k - 1]; bi[k - 1] = ti;
                                } else break;
                            }
                        }
                    }
                }
                // merge across the 4 lanes of the group (xor 1, 2 stay in-group)
                float wv[TOPK]; int wi[TOPK];
                int p = 0;
#pragma unroll
                for (int r = 0; r < TOPK; r++) {
                    float v = (p < TOPK) ? bv[p] : -FLT_MAX;
                    int id = (p < TOPK) ? bi[p] : 0x7fffffff;
#pragma unroll
                    for (int s = 1; s <= 2; s <<= 1) {
                        float ov = __shfl_xor_sync(0xffffffffu, v, s);
                        int oi = __shfl_xor_sync(0xffffffffu, id, s);
                        if (tk_better(ov, oi, v, id)) { v = ov; id = oi; }
                    }
                    if (p < TOPK && bi[p] == id) p++;
                    wv[r] = v; wi[r] = id;
                }
                if ((lane & 3) == 0) {
                    size_t base = (size_t)row * NCAND + blockIdx.x * 24 + wn * 6;
#pragma unroll
                    for (int r = 0; r < TOPK; r++) { cv[base + r] = wv[r]; ci[base + r] = wi[r]; }
                }
            }
        }
    }
}

// ================= merge candidates -> global top-6 -> edges =================
__global__ void topk_merge(const float* __restrict__ cv, const int* __restrict__ ci,
                           unsigned* __restrict__ bits, int mode) {
    int wid = (blockIdx.x * blockDim.x + threadIdx.x) >> 5;
    int lane = threadIdx.x & 31;
    if (wid >= NNODES) return;
    const int i = wid;
    float bv[TOPK]; int bi[TOPK];
#pragma unroll
    for (int k = 0; k < TOPK; k++) { bv[k] = -FLT_MAX; bi[k] = 0x7fffffff; }
    const float* rv = cv + (size_t)i * NCAND;
    const int* ri = ci + (size_t)i * NCAND;
#pragma unroll
    for (int it = 0; it < NCAND / 32; it++) {
        int idx = lane + it * 32;
        float v = rv[idx];
        int id = ri[idx];
        if (tk_better(v, id, bv[TOPK - 1], bi[TOPK - 1])) {
            bv[TOPK - 1] = v; bi[TOPK - 1] = id;
#pragma unroll
            for (int k = TOPK - 1; k > 0; k--) {
                if (tk_better(bv[k], bi[k], bv[k - 1], bi[k - 1])) {
                    float tv = bv[k]; bv[k] = bv[k - 1]; bv[k - 1] = tv;
                    int ti = bi[k]; bi[k] = bi[k - 1]; bi[k - 1] = ti;
                } else break;
            }
        }
    }
    int p = 0;
#pragma unroll
    for (int r = 0; r < TOPK; r++) {
        float v = (p < TOPK) ? bv[p] : -FLT_MAX;
        int id = (p < TOPK) ? bi[p] : 0x7fffffff;
#pragma unroll
        for (int s = 16; s; s >>= 1) {
            float ov = __shfl_xor_sync(0xffffffffu, v, s);
            int oi = __shfl_xor_sync(0xffffffffu, id, s);
            if (tk_better(ov, oi, v, id)) { v = ov; id = oi; }
        }
        if (p < TOPK && bi[p] == id) p++;
        if (lane == 0 && id < NNODES) {
            int j = id;
            bool ok = (j != i) && (mode == 0 || v > 0.f);
            if (ok) {
                atomicOr(&bits[(size_t)i * 64 + (j >> 5)], 1u << (j & 31));
                atomicOr(&bits[(size_t)j * 64 + (i >> 5)], 1u << (i & 31));
            }
        }
    }
}

// ================= neighbor lists from bitmask =================
__global__ void build_nbr_bits(const unsigned* __restrict__ bits, int* __restrict__ nbr,
                               int* __restrict__ cnt) {
    int warp = (blockIdx.x * blockDim.x + threadIdx.x) >> 5;
    int lane = threadIdx.x & 31;
    if (warp >= NNODES) return;
    const int i = warp;
    unsigned w0 = bits[(size_t)i * 64 + 2 * lane];
    unsigned w1 = bits[(size_t)i * 64 + 2 * lane + 1];
    int c = __popc(w0) + __popc(w1);
    int off = c;
#pragma unroll
    for (int s = 1; s < 32; s <<= 1) {
        int v = __shfl_up_sync(0xffffffffu, off, s);
        if (lane >= s) off += v;
    }
    int total = __shfl_sync(0xffffffffu, off, 31);
    off -= c;
    if (lane == 0) cnt[i] = total > MAXD ? MAXD : total;
    int base = lane * 64;
    int pos = off;
    while (w0) {
        int b = __ffs(w0) - 1; w0 &= w0 - 1;
        if (pos < MAXD) nbr[(size_t)i * MAXD + pos] = base + b;
        pos++;
    }
    base += 32;
    while (w1) {
        int b = __ffs(w1) - 1; w1 &= w1 - 1;
        if (pos < MAXD) nbr[(size_t)i * MAXD + pos] = base + b;
        pos++;
    }
}

// ================= attention scalars =================
__global__ void s12_kernel(const float* __restrict__ Wh, const float* __restrict__ a,
                           float* __restrict__ s1, float* __restrict__ s2, int Hn) {
    int warp = (blockIdx.x * blockDim.x + threadIdx.x) >> 5;
    int lane = threadIdx.x & 31;
    if (warp >= NNODES * Hn) return;
    int i = warp / Hn, h = warp % Hn;
    const float* w = Wh + (size_t)i * Hn * HIDD + (size_t)h * HIDD;
    const float* av = a + (size_t)h * 2 * HIDD;
    float a1 = 0.f, a2 = 0.f;
    for (int d = lane; d < HIDD; d += 32) {
        float x = w[d];
        a1 += x * av[d];
        a2 += x * av[HIDD + d];
    }
    for (int s = 16; s; s >>= 1) {
        a1 += __shfl_down_sync(0xffffffffu, a1, s);
        a2 += __shfl_down_sync(0xffffffffu, a2, s);
    }
    if (lane == 0) { s1[h * NNODES + i] = a1; s2[h * NNODES + i] = a2; }
}

// ================= sparse softmax-aggregate + ELU =================
__global__ void aggregate_kernel(const float* __restrict__ Wh,
                                 const int* __restrict__ nbr, const int* __restrict__ cnt,
                                 const float* __restrict__ s1, const float* __restrict__ s2,
                                 float* __restrict__ out, int Hn, int outStride, int outOff) {
    int b = blockIdx.x;
    int i = b / Hn, h = b % Hn;
    int t = threadIdx.x;  // 256 == HIDD
    __shared__ float w[MAXD];
    __shared__ float s_sum;
    int c = cnt[i];
    const int* nb = nbr + (size_t)i * MAXD;
    if (t < 32) {
        float m = -FLT_MAX;
        float base = s1[h * NNODES + i];
        for (int j = t; j < c; j += 32) {
            float e = base + s2[h * NNODES + nb[j]];
            e = e > 0.f ? e : 0.2f * e;  // leaky relu
            w[j] = e;
            m = fmaxf(m, e);
        }
        for (int s = 16; s; s >>= 1) m = fmaxf(m, __shfl_xor_sync(0xffffffffu, m, s));
        float sum = 0.f;
        for (int j = t; j < c; j += 32) {
            float ex = expf(w[j] - m);
            w[j] = ex;
            sum += ex;
        }
        for (int s = 16; s; s >>= 1) sum += __shfl_xor_sync(0xffffffffu, sum, s);
        if (t == 0) s_sum = sum;
    }
    __syncthreads();
    float acc = 0.f;
    for (int j = 0; j < c; j++)
        acc += w[j] * Wh[(size_t)nb[j] * (Hn * HIDD) + (size_t)h * HIDD + t];
    float v = acc / s_sum;
    v = v > 0.f ? v : expm1f(v);  // elu
    out[(size_t)i * outStride + outOff + (size_t)h * HIDD + t] = v;
}

// ================= final MLP layer (N=1) =================
__global__ void mlp3_kernel(const float* __restrict__ Xin, const float* __restrict__ W,
                            const float* __restrict__ b, float* __restrict__ out) {
    int warp = (blockIdx.x * blockDim.x + threadIdx.x) >> 5;
    int lane = threadIdx.x & 31;
    if (warp >= NNODES) return;
    float acc = 0.f;
    for (int d = lane; d < 128; d += 32) acc += Xin[(size_t)warp * 128 + d] * W[d];
    for (int s = 16; s; s >>= 1) acc += __shfl_down_sync(0xffffffffu, acc, s);
    if (lane == 0) out[warp] = acc + b[0];
}

// ================= host side =================
#define GETSYM(p, s)                               \
    do {                                           \
        void* _tmp = nullptr;                      \
        cudaGetSymbolAddress(&_tmp, s);            \
        p = (decltype(p))_tmp;                     \
    } while (0)

struct Branch {
    float *sq, *cv, *Wh, *s1, *s2, *hidden, *WhO, *sO1, *sO2;
    int* civ;
    __nv_bfloat16 *Ap, *Bp, *Wp;
    unsigned* bits;
    int *nbr, *cnt;
};

static inline void launch_mma(cudaStream_t st, const __nv_bfloat16* A, const __nv_bfloat16* B,
                              float* C, int M, int Nc, int Kp, const float* bias, int relu) {
    mma_gemm_t<false><<<dim3(Nc / 128, M / 128), 256, MMA_SMEM_BYTES, st>>>(
        A, B, C, Nc, Kp, bias, relu, nullptr, nullptr, nullptr, 0);
}

static void run_gat(cudaStream_t st, const Branch& b, const float* X, float* Xn, int mode,
                    const float* W_h, const float* a_h, const float* W_o, const float* a_o,
                    float* pair, int pairOff) {
    rowstat_kernel<<<NNODES, 256, 0, st>>>(X, mode ? Xn : nullptr, b.sq);
    const float* Xs = mode ? Xn : X;
    // sim + fused per-segment top-6 candidates (no sim materialization)
    pack3AB_kernel<<<(NNODES * DIM + 255) / 256, 256, 0, st>>>(Xs, b.Ap, b.Bp, DIM, NNODES * DIM);
    mma_gemm_t<true><<<dim3(NNODES / 128, NNODES / 128), 256, MMA_SMEM_BYTES, st>>>(
        b.Ap, b.Bp, nullptr, NNODES, 3 * DIM, nullptr, 0, b.cv, b.civ, b.sq, mode);
    cudaMemsetAsync(b.bits, 0, (size_t)NNODES * 64 * sizeof(unsigned), st);
    topk_merge<<<NNODES / 8, 256, 0, st>>>(b.cv, b.civ, b.bits, mode);
    build_nbr_bits<<<NNODES / 8, 256, 0, st>>>(b.bits, b.nbr, b.cnt);
    // Wh = X @ W_h
    if (mode)
        pack3_kernel<<<(NNODES * DIM + 255) / 256, 256, 0, st>>>(X, b.Ap, DIM, NNODES * DIM, 0);
    packWh3_kernel<<<(NHEAD * HIDD * DIM + 255) / 256, 256, 0, st>>>(W_h, b.Wp);
    launch_mma(st, b.Ap, b.Wp, b.Wh, NNODES, NHEAD * HIDD, 3 * DIM, nullptr, 0);
    s12_kernel<<<(NNODES * NHEAD) / 4, 128, 0, st>>>(b.Wh, a_h, b.s1, b.s2, NHEAD);
    aggregate_kernel<<<NNODES * NHEAD, 256, 0, st>>>(b.Wh, b.nbr, b.cnt, b.s1, b.s2, b.hidden,
                                                     NHEAD, NHEAD * HIDD, 0);
    // WhO = hidden @ W_o
    pack3_kernel<<<(NNODES * 1024 + 255) / 256, 256, 0, st>>>(b.hidden, b.Ap, 1024,
                                                              NNODES * 1024, 0);
    packWgen3_kernel<<<(1024 * HIDD + 255) / 256, 256, 0, st>>>(W_o, b.Wp, 1024, HIDD);
    launch_mma(st, b.Ap, b.Wp, b.WhO, NNODES, HIDD, 3 * 1024, nullptr, 0);
    s12_kernel<<<NNODES / 4, 128, 0, st>>>(b.WhO, a_o, b.sO1, b.sO2, 1);
    aggregate_kernel<<<NNODES, 256, 0, st>>>(b.WhO, b.nbr, b.cnt, b.sO1, b.sO2, pair, 1, 2 * HIDD,
                                             pairOff);
}

extern "C" void kernel_launch(void* const* d_in, const int* in_sizes, int n_in,
                              void* d_out, int out_size) {
    const float* user_nodes = (const float*)d_in[0];
    const float* food_nodes = (const float*)d_in[1];
    const float* user_W_h = (const float*)d_in[2];
    const float* user_a_h = (const float*)d_in[3];
    const float* user_W_o = (const float*)d_in[4];
    const float* user_a_o = (const float*)d_in[5];
    const float* food_W_h = (const float*)d_in[6];
    const float* food_a_h = (const float*)d_in[7];
    const float* food_W_o = (const float*)d_in[8];
    const float* food_a_o = (const float*)d_in[9];
    const float* mlp_W0 = (const float*)d_in[10];
    const float* mlp_b0 = (const float*)d_in[11];
    const float* mlp_W1 = (const float*)d_in[12];
    const float* mlp_b1 = (const float*)d_in[13];
    const float* mlp_W2 = (const float*)d_in[14];
    const float* mlp_b2 = (const float*)d_in[15];
    const float* mlp_W3 = (const float*)d_in[16];
    const float* mlp_b3 = (const float*)d_in[17];

    static cudaStream_t s_food = nullptr;
    static cudaEvent_t ev_fork = nullptr, ev_join = nullptr;
    if (!s_food) {
        cudaStreamCreateWithFlags(&s_food, cudaStreamNonBlocking);
        cudaEventCreateWithFlags(&ev_fork, cudaEventDisableTiming);
        cudaEventCreateWithFlags(&ev_join, cudaEventDisableTiming);
        cudaFuncSetAttribute(mma_gemm_t<false>, cudaFuncAttributeMaxDynamicSharedMemorySize,
                             MMA_SMEM_BYTES);
        cudaFuncSetAttribute(mma_gemm_t<true>, cudaFuncAttributeMaxDynamicSharedMemorySize,
                             MMA_SMEM_BYTES);
    }

    float* Xn;  GETSYM(Xn, g_Xn);
    float* pair; GETSYM(pair, g_pair);
    float *m1, *m2, *m3;
    GETSYM(m1, g_m1); GETSYM(m2, g_m2); GETSYM(m3, g_m3);

    Branch br[2];
    for (int b = 0; b < 2; b++) {
        void* t;
        cudaGetSymbolAddress(&t, g_sq);     br[b].sq  = (float*)t + (size_t)b * NNODES;
        cudaGetSymbolAddress(&t, g_cand_v); br[b].cv  = (float*)t + (size_t)b * NNODES * NCAND;
        cudaGetSymbolAddress(&t, g_cand_i); br[b].civ = (int*)t + (size_t)b * NNODES * NCAND;
        cudaGetSymbolAddress(&t, g_Ap);     br[b].Ap  = (__nv_bfloat16*)t + (size_t)b * NNODES * 3 * 1024;
        cudaGetSymbolAddress(&t, g_Bp);     br[b].Bp  = (__nv_bfloat16*)t + (size_t)b * NNODES * 3 * DIM;
        cudaGetSymbolAddress(&t, g_Wp);     br[b].Wp  = (__nv_bfloat16*)t + (size_t)b * 1024 * 3 * 1024;
        cudaGetSymbolAddress(&t, g_bits);   br[b].bits = (unsigned*)t + (size_t)b * NNODES * 64;
        cudaGetSymbolAddress(&t, g_nbr);    br[b].nbr = (int*)t + (size_t)b * NNODES * MAXD;
        cudaGetSymbolAddress(&t, g_cnt);    br[b].cnt = (int*)t + (size_t)b * NNODES;
        cudaGetSymbolAddress(&t, g_Wh);     br[b].Wh  = (float*)t + (size_t)b * NNODES * NHEAD * HIDD;
        cudaGetSymbolAddress(&t, g_s1);     br[b].s1  = (float*)t + (size_t)b * NHEAD * NNODES;
        cudaGetSymbolAddress(&t, g_s2);     br[b].s2  = (float*)t + (size_t)b * NHEAD * NNODES;
        cudaGetSymbolAddress(&t, g_hidden); br[b].hidden = (float*)t + (size_t)b * NNODES * NHEAD * HIDD;
        cudaGetSymbolAddress(&t, g_WhO);    br[b].WhO = (float*)t + (size_t)b * NNODES * HIDD;
        cudaGetSymbolAddress(&t, g_sO1);    br[b].sO1 = (float*)t + (size_t)b * NNODES;
        cudaGetSymbolAddress(&t, g_sO2);    br[b].sO2 = (float*)t + (size_t)b * NNODES;
    }

    // fork: food branch runs on s_food concurrently with user branch on stream 0
    cudaEventRecord(ev_fork, 0);
    cudaStreamWaitEvent(s_food, ev_fork, 0);

    run_gat(0, br[0], user_nodes, nullptr, 0, user_W_h, user_a_h, user_W_o, user_a_o, pair, 0);
    run_gat(s_food, br[1], food_nodes, Xn, 1, food_W_h, food_a_h, food_W_o, food_a_o, pair, HIDD);

    // join
    cudaEventRecord(ev_join, s_food);
    cudaStreamWaitEvent(0, ev_join, 0);

    // MLP: 512 -> 512 -> 256 -> 128 -> 1
    pack3_kernel<<<(NNODES * 512 + 255) / 256, 256>>>(pair, br[0].Ap, 512, NNODES * 512, 0);
    packWgen3_kernel<<<(512 * 512 + 255) / 256, 256>>>(mlp_W0, br[0].Wp, 512, 512);
    launch_mma(0, br[0].Ap, br[0].Wp, m1, NNODES, 512, 3 * 512, mlp_b0, 1);

    pack3_kernel<<<(NNODES * 512 + 255) / 256, 256>>>(m1, br[0].Ap, 512, NNODES * 512, 0);
    packWgen3_kernel<<<(512 * 256 + 255) / 256, 256>>>(mlp_W1, br[0].Wp, 512, 256);
    launch_mma(0, br[0].Ap, br[0].Wp, m2, NNODES, 256, 3 * 512, mlp_b1, 1);

    pack3_kernel<<<(NNODES * 256 + 255) / 256, 256>>>(m2, br[0].Ap, 256, NNODES * 256, 0);
    packWgen3_kernel<<<(256 * 128 + 255) / 256, 256>>>(mlp_W2, br[0].Wp, 256, 128);
    launch_mma(0, br[0].Ap, br[0].Wp, m3, NNODES, 128, 3 * 256, mlp_b2, 1);

    mlp3_kernel<<<NNODES / 4, 128>>>(m3, mlp_W3, mlp_b3, (float*)d_out);

    (void)in_sizes; (void)n_in; (void)out_size;
}

// round 11
// speedup vs baseline: 1.1377x; 1.1377x over previous
#include <cuda_runtime.h>
#include <cuda_bf16.h>
#include <float.h>
#include <math.h>
#include <cstdint>

#define NNODES 2048
#define DIM    512
#define HIDD   256
#define NHEAD  4
#define TOPK   6
#define MAXD   256

// ================= scratch (device globals; per-branch where concurrent) =================
__device__ __align__(16) float g_Xn[NNODES * DIM];
__device__ __align__(16) float g_sq[2][NNODES];
__device__ __align__(16) float g_sim[2][NNODES * NNODES];
__device__ __align__(16) __nv_bfloat16 g_Ap[2][NNODES * 3 * 1024];
__device__ __align__(16) __nv_bfloat16 g_Bp[2][NNODES * 3 * DIM];
__device__ __align__(16) __nv_bfloat16 g_Wp[2][1024 * 3 * 1024];
__device__ __align__(16) __nv_bfloat16 g_pairP[NNODES * 3 * 512];
__device__ __align__(16) __nv_bfloat16 g_m1P[NNODES * 3 * 512];
__device__ __align__(16) __nv_bfloat16 g_m2P[NNODES * 3 * 256];
__device__ unsigned g_bits[2][NNODES * 64];
__device__ int   g_nbr[2][NNODES * MAXD];
__device__ int   g_cnt[2][NNODES];
__device__ __align__(16) float g_Wh[2][NNODES * NHEAD * HIDD];
__device__ __align__(16) float g_s1[2][NHEAD * NNODES];
__device__ __align__(16) float g_s2[2][NHEAD * NNODES];
__device__ __align__(16) float g_WhO[2][NNODES * HIDD];
__device__ __align__(16) float g_sO1[2][NNODES];
__device__ __align__(16) float g_sO2[2][NNODES];
__device__ __align__(16) float g_m3[NNODES * 128];

// ================= small PTX helpers =================
__device__ __forceinline__ uint32_t smem_to_u32(const void* p) {
    uint32_t a;
    asm("{ .reg .u64 t; cvta.to.shared.u64 t, %1; cvt.u32.u64 %0, t; }" : "=r"(a) : "l"(p));
    return a;
}
__device__ __forceinline__ void cp_async16(uint32_t saddr, const void* gaddr) {
    asm volatile("cp.async.cg.shared.global [%0], [%1], 16;" :: "r"(saddr), "l"(gaddr));
}
__device__ __forceinline__ void cp_commit() { asm volatile("cp.async.commit_group;"); }
template <int N>
__device__ __forceinline__ void cp_wait() { asm volatile("cp.async.wait_group %0;" :: "n"(N)); }

__device__ __forceinline__ void ldmatrix_x4(uint32_t* r, uint32_t addr) {
    asm volatile("ldmatrix.sync.aligned.m8n8.x4.shared.b16 {%0,%1,%2,%3}, [%4];"
                 : "=r"(r[0]), "=r"(r[1]), "=r"(r[2]), "=r"(r[3]) : "r"(addr));
}
__device__ __forceinline__ void ldmatrix_x2(uint32_t* r, uint32_t addr) {
    asm volatile("ldmatrix.sync.aligned.m8n8.x2.shared.b16 {%0,%1}, [%2];"
                 : "=r"(r[0]), "=r"(r[1]) : "r"(addr));
}
__device__ __forceinline__ void mma16816(float* c, const uint32_t* a, const uint32_t* b) {
    asm volatile(
        "mma.sync.aligned.m16n8k16.row.col.f32.bf16.bf16.f32 "
        "{%0,%1,%2,%3}, {%4,%5,%6,%7}, {%8,%9}, {%0,%1,%2,%3};"
        : "+f"(c[0]), "+f"(c[1]), "+f"(c[2]), "+f"(c[3])
        : "r"(a[0]), "r"(a[1]), "r"(a[2]), "r"(a[3]), "r"(b[0]), "r"(b[1]));
}

__device__ __forceinline__ bool tk_better(float v1, int i1, float v2, int i2) {
    return (v1 > v2) || (v1 == v2 && i1 < i2);
}

// ================= row norms =================
__global__ void rowstat_kernel(const float* __restrict__ X, float* __restrict__ Xn,
                               float* __restrict__ sq) {
    int i = blockIdx.x;
    int t = threadIdx.x;  // 256
    float s = 0.f;
    for (int d = t; d < DIM; d += 256) { float v = X[(size_t)i * DIM + d]; s += v * v; }
    __shared__ float sh[256];
    sh[t] = s; __syncthreads();
    for (int k = 128; k; k >>= 1) { if (t < k) sh[t] += sh[t + k]; __syncthreads(); }
    float tot = sh[0];
    if (t == 0) sq[i] = tot;
    if (Xn) {
        float inv = 1.0f / sqrtf(tot);
        for (int d = t; d < DIM; d += 256) Xn[(size_t)i * DIM + d] = X[(size_t)i * DIM + d] * inv;
    }
}

// ================= packing =================
// A pattern: [hi | hi | lo] ; B pattern: [hi | lo | hi]
__global__ void pack3_kernel(const float* __restrict__ src, __nv_bfloat16* __restrict__ dst,
                             int K, int total, int pat) {
    int idx = blockIdx.x * blockDim.x + threadIdx.x;
    if (idx >= total) return;
    int row = idx / K, col = idx % K;
    float x = src[idx];
    __nv_bfloat16 hi = __float2bfloat16(x);
    __nv_bfloat16 lo = __float2bfloat16(x - __bfloat162float(hi));
    size_t base = (size_t)row * 3 * K + col;
    dst[base] = hi;
    dst[base + K] = pat ? lo : hi;
    dst[base + 2 * K] = pat ? hi : lo;
}

__global__ void pack3AB_kernel(const float* __restrict__ src, __nv_bfloat16* __restrict__ dA,
                               __nv_bfloat16* __restrict__ dB, int K, int total) {
    int idx = blockIdx.x * blockDim.x + threadIdx.x;
    if (idx >= total) return;
    int row = idx / K, col = idx % K;
    float x = src[idx];
    __nv_bfloat16 hi = __float2bfloat16(x);
    __nv_bfloat16 lo = __float2bfloat16(x - __bfloat162float(hi));
    size_t base = (size_t)row * 3 * K + col;
    dA[base] = hi; dA[base + K] = hi; dA[base + 2 * K] = lo;
    dB[base] = hi; dB[base + K] = lo; dB[base + 2 * K] = hi;
}

__global__ void packWh3_kernel(const float* __restrict__ W, __nv_bfloat16* __restrict__ dst) {
    int idx = blockIdx.x * blockDim.x + threadIdx.x;
    if (idx >= NHEAD * HIDD * DIM) return;
    int n = idx / DIM, k = idx % DIM;
    int h = n / HIDD, hid = n % HIDD;
    float w = W[(size_t)h * DIM * HIDD + (size_t)k * HIDD + hid];
    __nv_bfloat16 hi = __float2bfloat16(w);
    __nv_bfloat16 lo = __float2bfloat16(w - __bfloat162float(hi));
    size_t base = (size_t)n * 3 * DIM + k;
    dst[base] = hi; dst[base + DIM] = lo; dst[base + 2 * DIM] = hi;
}

__global__ void packWgen3_kernel(const float* __restrict__ W, __nv_bfloat16* __restrict__ dst,
                                 int K, int N) {
    int idx = blockIdx.x * blockDim.x + threadIdx.x;
    if (idx >= N * K) return;
    int n = idx / K, k = idx % K;
    float w = W[(size_t)k * N + n];
    __nv_bfloat16 hi = __float2bfloat16(w);
    __nv_bfloat16 lo = __float2bfloat16(w - __bfloat162float(hi));
    size_t base = (size_t)n * 3 * K + k;
    dst[base] = hi; dst[base + K] = lo; dst[base + 2 * K] = hi;
}

// ================= mma.sync bf16 GEMM, 3-stage pipeline =================
// C[M,Nc] = A[M,K] @ B[Nc,K]^T ; 128x128 tile, BK=64, SW128 swizzle, 8 warps (2x4).
// If packOut != null, also/instead write bf16 [hi|hi|lo] packed rows (K' = 3*Nc).
#define MMA_STAGES 3
#define MMA_SMEM_BYTES (MMA_STAGES * 32768)

__global__ void __launch_bounds__(256, 2)
mma_gemm(const __nv_bfloat16* __restrict__ A, const __nv_bfloat16* __restrict__ B,
         float* __restrict__ C, int Nc, int K, const float* __restrict__ bias, int relu,
         __nv_bfloat16* __restrict__ packOut) {
    extern __shared__ char sm[];
    const int tid = threadIdx.x;
    const int lane = tid & 31;
    const int warp = tid >> 5;
    const int wm = warp >> 2;   // 0..1
    const int wn = warp & 3;    // 0..3
    const int row0 = blockIdx.y * 128;
    const int col0 = blockIdx.x * 128;
    const uint32_t sbase = smem_to_u32(sm);

    const __nv_bfloat16* Aptr = A + (size_t)row0 * K;
    const __nv_bfloat16* Bptr = B + (size_t)col0 * K;

    float acc[4][4][4];
#pragma unroll
    for (int mt = 0; mt < 4; mt++)
#pragma unroll
        for (int nt = 0; nt < 4; nt++)
#pragma unroll
            for (int q = 0; q < 4; q++) acc[mt][nt][q] = 0.f;

    const int nch = K / 64;
    auto issue = [&](int c) {
        uint32_t base = sbase + (c % MMA_STAGES) * 32768;
        int koff = c * 64;
#pragma unroll
        for (int l = 0; l < 4; l++) {
            int idx = tid + l * 256;
            int r = idx >> 3;
            int jb = (idx & 7) * 16;
            unsigned off = r * 128 + jb;
            unsigned sw = off ^ ((off >> 3) & 0x70);
            cp_async16(base + sw, (const char*)(Aptr + (size_t)r * K + koff) + jb);
            cp_async16(base + 16384 + sw, (const char*)(Bptr + (size_t)r * K + koff) + jb);
        }
        cp_commit();
    };

    issue(0);
    issue(1);
    for (int c = 0; c < nch; c++) {
        cp_wait<1>();
        __syncthreads();
        if (c + 2 < nch) issue(c + 2); else cp_commit();
        uint32_t aBase = sbase + (c % MMA_STAGES) * 32768;
        uint32_t bBase = aBase + 16384;
#pragma unroll
        for (int ks = 0; ks < 4; ks++) {
            uint32_t af[4][4], bf[4][2];
#pragma unroll
            for (int mt = 0; mt < 4; mt++) {
                int r = wm * 64 + mt * 16 + (lane & 15);
                unsigned off = r * 128 + ks * 32 + (lane >> 4) * 16;
                unsigned sw = off ^ ((off >> 3) & 0x70);
                ldmatrix_x4(af[mt], aBase + sw);
            }
#pragma unroll
            for (int nt = 0; nt < 4; nt++) {
                int r = wn * 32 + nt * 8 + (lane & 7);
                unsigned off = r * 128 + ks * 32 + ((lane >> 3) & 1) * 16;
                unsigned sw = off ^ ((off >> 3) & 0x70);
                ldmatrix_x2(bf[nt], bBase + sw);
            }
#pragma unroll
            for (int mt = 0; mt < 4; mt++)
#pragma unroll
                for (int nt = 0; nt < 4; nt++)
                    mma16816(acc[mt][nt], af[mt], bf[nt]);
        }
        __syncthreads();
    }

#pragma unroll
    for (int mt = 0; mt < 4; mt++) {
        int r0 = row0 + wm * 64 + mt * 16 + (lane >> 2);
#pragma unroll
        for (int nt = 0; nt < 4; nt++) {
            int cc = col0 + wn * 32 + nt * 8 + (lane & 3) * 2;
            float b0 = 0.f, b1 = 0.f;
            if (bias) { b0 = bias[cc]; b1 = bias[cc + 1]; }
            float v0 = acc[mt][nt][0] + b0, v1 = acc[mt][nt][1] + b1;
            float v2 = acc[mt][nt][2] + b0, v3 = acc[mt][nt][3] + b1;
            if (relu) {
                v0 = fmaxf(v0, 0.f); v1 = fmaxf(v1, 0.f);
                v2 = fmaxf(v2, 0.f); v3 = fmaxf(v3, 0.f);
            }
            if (C) {
                *(float2*)(C + (size_t)r0 * Nc + cc) = make_float2(v0, v1);
                *(float2*)(C + (size_t)(r0 + 8) * Nc + cc) = make_float2(v2, v3);
            }
            if (packOut) {
                __nv_bfloat16 h0 = __float2bfloat16(v0), h1 = __float2bfloat16(v1);
                __nv_bfloat16 l0 = __float2bfloat16(v0 - __bfloat162float(h0));
                __nv_bfloat16 l1 = __float2bfloat16(v1 - __bfloat162float(h1));
                __nv_bfloat16 h2 = __float2bfloat16(v2), h3 = __float2bfloat16(v3);
                __nv_bfloat16 l2 = __float2bfloat16(v2 - __bfloat162float(h2));
                __nv_bfloat16 l3 = __float2bfloat16(v3 - __bfloat162float(h3));
                __nv_bfloat16* p0 = packOut + (size_t)r0 * 3 * Nc + cc;
                __nv_bfloat16* p1 = packOut + (size_t)(r0 + 8) * 3 * Nc + cc;
                *(__nv_bfloat162*)(p0) = __nv_bfloat162(h0, h1);
                *(__nv_bfloat162*)(p0 + Nc) = __nv_bfloat162(h0, h1);
                *(__nv_bfloat162*)(p0 + 2 * Nc) = __nv_bfloat162(l0, l1);
                *(__nv_bfloat162*)(p1) = __nv_bfloat162(h2, h3);
                *(__nv_bfloat162*)(p1 + Nc) = __nv_bfloat162(h2, h3);
                *(__nv_bfloat162*)(p1 + 2 * Nc) = __nv_bfloat162(l2, l3);
            }
        }
    }
}

// ================= top-6 + edges into bitmask (register-batched loads) =================
__global__ void topk_kernel2(const float* __restrict__ sim, const float* __restrict__ sq,
                             unsigned* __restrict__ bits, int mode) {
    const int i = blockIdx.x;
    const int t = threadIdx.x;  // 128
    const int w = t >> 5, lane = t & 31;
    float bv[TOPK]; int bi[TOPK];
#pragma unroll
    for (int k = 0; k < TOPK; k++) { bv[k] = -FLT_MAX; bi[k] = 0x7fffffff; }
    const float4* row = (const float4*)(sim + (size_t)i * NNODES);
    // batch all 4 loads before the compare chains (MLP=4)
    float4 rv[4];
#pragma unroll
    for (int it = 0; it < 4; it++) rv[it] = row[w * 128 + it * 32 + lane];
#pragma unroll
    for (int it = 0; it < 4; it++) {
        int c4 = w * 128 + it * 32 + lane;
        float e[4] = {rv[it].x, rv[it].y, rv[it].z, rv[it].w};
#pragma unroll
        for (int j = 0; j < 4; j++) {
            int c = c4 * 4 + j;
            float key = (mode == 0) ? (2.f * e[j] - sq[c]) : e[j];
            if (tk_better(key, c, bv[TOPK - 1], bi[TOPK - 1])) {
                bv[TOPK - 1] = key; bi[TOPK - 1] = c;
#pragma unroll
                for (int k = TOPK - 1; k > 0; k--) {
                    if (tk_better(bv[k], bi[k], bv[k - 1], bi[k - 1])) {
                        float tv = bv[k]; bv[k] = bv[k - 1]; bv[k - 1] = tv;
                        int ti = bi[k]; bi[k] = bi[k - 1]; bi[k - 1] = ti;
                    } else break;
                }
            }
        }
    }
    __shared__ float sv[4 * TOPK];
    __shared__ int si[4 * TOPK];
    {
        int p = 0;
#pragma unroll
        for (int r = 0; r < TOPK; r++) {
            float v = (p < TOPK) ? bv[p] : -FLT_MAX;
            int id = (p < TOPK) ? bi[p] : 0x7fffffff;
#pragma unroll
            for (int s = 16; s; s >>= 1) {
                float ov = __shfl_xor_sync(0xffffffffu, v, s);
                int oi = __shfl_xor_sync(0xffffffffu, id, s);
                if (tk_better(ov, oi, v, id)) { v = ov; id = oi; }
            }
            if (p < TOPK && bi[p] == id) p++;
            if (lane == 0) { sv[w * TOPK + r] = v; si[w * TOPK + r] = id; }
        }
    }
    __syncthreads();
    if (w == 0) {
        float v = (lane < 4 * TOPK) ? sv[lane] : -FLT_MAX;
        int id = (lane < 4 * TOPK) ? si[lane] : 0x7fffffff;
#pragma unroll
        for (int r = 0; r < TOPK; r++) {
            float mv = v; int mi = id;
#pragma unroll
            for (int s = 16; s; s >>= 1) {
                float ov = __shfl_xor_sync(0xffffffffu, mv, s);
                int oi = __shfl_xor_sync(0xffffffffu, mi, s);
                if (tk_better(ov, oi, mv, mi)) { mv = ov; mi = oi; }
            }
            if (id == mi) { v = -FLT_MAX; id = 0x7fffffff; }
            if (lane == 0 && mi < NNODES) {
                int j = mi;
                bool ok = (j != i) && (mode == 0 || mv > 0.f);
                if (ok) {
                    atomicOr(&bits[(size_t)i * 64 + (j >> 5)], 1u << (j & 31));
                    atomicOr(&bits[(size_t)j * 64 + (i >> 5)], 1u << (i & 31));
                }
            }
        }
    }
}

// ================= neighbor lists from bitmask =================
__global__ void build_nbr_bits(const unsigned* __restrict__ bits, int* __restrict__ nbr,
                               int* __restrict__ cnt) {
    int warp = (blockIdx.x * blockDim.x + threadIdx.x) >> 5;
    int lane = threadIdx.x & 31;
    if (warp >= NNODES) return;
    const int i = warp;
    unsigned w0 = bits[(size_t)i * 64 + 2 * lane];
    unsigned w1 = bits[(size_t)i * 64 + 2 * lane + 1];
    int c = __popc(w0) + __popc(w1);
    int off = c;
#pragma unroll
    for (int s = 1; s < 32; s <<= 1) {
        int v = __shfl_up_sync(0xffffffffu, off, s);
        if (lane >= s) off += v;
    }
    int total = __shfl_sync(0xffffffffu, off, 31);
    off -= c;
    if (lane == 0) cnt[i] = total > MAXD ? MAXD : total;
    int base = lane * 64;
    int pos = off;
    while (w0) {
        int b = __ffs(w0) - 1; w0 &= w0 - 1;
        if (pos < MAXD) nbr[(size_t)i * MAXD + pos] = base + b;
        pos++;
    }
    base += 32;
    while (w1) {
        int b = __ffs(w1) - 1; w1 &= w1 - 1;
        if (pos < MAXD) nbr[(size_t)i * MAXD + pos] = base + b;
        pos++;
    }
}

// ================= attention scalars =================
__global__ void s12_kernel(const float* __restrict__ Wh, const float* __restrict__ a,
                           float* __restrict__ s1, float* __restrict__ s2, int Hn) {
    int warp = (blockIdx.x * blockDim.x + threadIdx.x) >> 5;
    int lane = threadIdx.x & 31;
    if (warp >= NNODES * Hn) return;
    int i = warp / Hn, h = warp % Hn;
    const float* w = Wh + (size_t)i * Hn * HIDD + (size_t)h * HIDD;
    const float* av = a + (size_t)h * 2 * HIDD;
    float a1 = 0.f, a2 = 0.f;
    for (int d = lane; d < HIDD; d += 32) {
        float x = w[d];
        a1 += x * av[d];
        a2 += x * av[HIDD + d];
    }
    for (int s = 16; s; s >>= 1) {
        a1 += __shfl_down_sync(0xffffffffu, a1, s);
        a2 += __shfl_down_sync(0xffffffffu, a2, s);
    }
    if (lane == 0) { s1[h * NNODES + i] = a1; s2[h * NNODES + i] = a2; }
}

// ================= sparse softmax-aggregate + ELU (+ optional packed output) =================
__global__ void aggregate_kernel(const float* __restrict__ Wh,
                                 const int* __restrict__ nbr, const int* __restrict__ cnt,
                                 const float* __restrict__ s1, const float* __restrict__ s2,
                                 float* __restrict__ out, int Hn, int outStride, int outOff,
                                 __nv_bfloat16* __restrict__ pout, int pK) {
    int b = blockIdx.x;
    int i = b / Hn, h = b % Hn;
    int t = threadIdx.x;  // 256 == HIDD
    __shared__ float w[MAXD];
    __shared__ float s_sum;
    int c = cnt[i];
    const int* nb = nbr + (size_t)i * MAXD;
    if (t < 32) {
        float m = -FLT_MAX;
        float base = s1[h * NNODES + i];
        for (int j = t; j < c; j += 32) {
            float e = base + s2[h * NNODES + nb[j]];
            e = e > 0.f ? e : 0.2f * e;  // leaky relu
            w[j] = e;
            m = fmaxf(m, e);
        }
        for (int s = 16; s; s >>= 1) m = fmaxf(m, __shfl_xor_sync(0xffffffffu, m, s));
        float sum = 0.f;
        for (int j = t; j < c; j += 32) {
            float ex = expf(w[j] - m);
            w[j] = ex;
            sum += ex;
        }
        for (int s = 16; s; s >>= 1) sum += __shfl_xor_sync(0xffffffffu, sum, s);
        if (t == 0) s_sum = sum;
    }
    __syncthreads();
    float acc = 0.f;
    for (int j = 0; j < c; j++)
        acc += w[j] * Wh[(size_t)nb[j] * (Hn * HIDD) + (size_t)h * HIDD + t];
    float v = acc / s_sum;
    v = v > 0.f ? v : expm1f(v);  // elu
    int col = outOff + h * HIDD + t;
    if (out) out[(size_t)i * outStride + col] = v;
    if (pout) {
        __nv_bfloat16 hi = __float2bfloat16(v);
        __nv_bfloat16 lo = __float2bfloat16(v - __bfloat162float(hi));
        size_t base = (size_t)i * 3 * pK + col;
        pout[base] = hi; pout[base + pK] = hi; pout[base + 2 * pK] = lo;
    }
}

// ================= final MLP layer (N=1) =================
__global__ void mlp3_kernel(const float* __restrict__ Xin, const float* __restrict__ W,
                            const float* __restrict__ b, float* __restrict__ out) {
    int warp = (blockIdx.x * blockDim.x + threadIdx.x) >> 5;
    int lane = threadIdx.x & 31;
    if (warp >= NNODES) return;
    float acc = 0.f;
    for (int d = lane; d < 128; d += 32) acc += Xin[(size_t)warp * 128 + d] * W[d];
    for (int s = 16; s; s >>= 1) acc += __shfl_down_sync(0xffffffffu, acc, s);
    if (lane == 0) out[warp] = acc + b[0];
}

// ================= host side =================
#define GETSYM(p, s)                               \
    do {                                           \
        void* _tmp = nullptr;                      \
        cudaGetSymbolAddress(&_tmp, s);            \
        p = (decltype(p))_tmp;                     \
    } while (0)

struct Branch {
    float *sq, *sim, *Wh, *s1, *s2, *WhO, *sO1, *sO2;
    __nv_bfloat16 *Ap, *Bp, *Wp;
    unsigned* bits;
    int *nbr, *cnt;
};

static inline void launch_mma(cudaStream_t st, const __nv_bfloat16* A, const __nv_bfloat16* B,
                              float* C, int M, int Nc, int Kp, const float* bias, int relu,
                              __nv_bfloat16* packOut) {
    mma_gemm<<<dim3(Nc / 128, M / 128), 256, MMA_SMEM_BYTES, st>>>(A, B, C, Nc, Kp, bias, relu,
                                                                   packOut);
}

static void run_gat(cudaStream_t st, const Branch& b, const float* X, float* Xn, int mode,
                    const float* W_h, const float* a_h, const float* W_o, const float* a_o,
                    __nv_bfloat16* pairP, int pairOff) {
    rowstat_kernel<<<NNODES, 256, 0, st>>>(X, mode ? Xn : nullptr, b.sq);
    const float* Xs = mode ? Xn : X;
    // sim = Xs @ Xs^T (split bf16)
    pack3AB_kernel<<<(NNODES * DIM + 255) / 256, 256, 0, st>>>(Xs, b.Ap, b.Bp, DIM, NNODES * DIM);
    launch_mma(st, b.Ap, b.Bp, b.sim, NNODES, NNODES, 3 * DIM, nullptr, 0, nullptr);
    cudaMemsetAsync(b.bits, 0, (size_t)NNODES * 64 * sizeof(unsigned), st);
    topk_kernel2<<<NNODES, 128, 0, st>>>(b.sim, b.sq, b.bits, mode);
    build_nbr_bits<<<NNODES / 8, 256, 0, st>>>(b.bits, b.nbr, b.cnt);
    // Wh = X @ W_h (fp32 out for s12/aggregate)
    if (mode)
        pack3_kernel<<<(NNODES * DIM + 255) / 256, 256, 0, st>>>(X, b.Ap, DIM, NNODES * DIM, 0);
    packWh3_kernel<<<(NHEAD * HIDD * DIM + 255) / 256, 256, 0, st>>>(W_h, b.Wp);
    launch_mma(st, b.Ap, b.Wp, b.Wh, NNODES, NHEAD * HIDD, 3 * DIM, nullptr, 0, nullptr);
    s12_kernel<<<(NNODES * NHEAD) / 4, 128, 0, st>>>(b.Wh, a_h, b.s1, b.s2, NHEAD);
    // hidden aggregate writes packed A for the Wo GEMM directly (no fp32 hidden)
    aggregate_kernel<<<NNODES * NHEAD, 256, 0, st>>>(b.Wh, b.nbr, b.cnt, b.s1, b.s2,
                                                     nullptr, NHEAD, 0, 0, b.Ap, 1024);
    // WhO = hidden @ W_o
    packWgen3_kernel<<<(1024 * HIDD + 255) / 256, 256, 0, st>>>(W_o, b.Wp, 1024, HIDD);
    launch_mma(st, b.Ap, b.Wp, b.WhO, NNODES, HIDD, 3 * 1024, nullptr, 0, nullptr);
    s12_kernel<<<NNODES / 4, 128, 0, st>>>(b.WhO, a_o, b.sO1, b.sO2, 1);
    // output aggregate writes packed pair for MLP0 directly
    aggregate_kernel<<<NNODES, 256, 0, st>>>(b.WhO, b.nbr, b.cnt, b.sO1, b.sO2,
                                             nullptr, 1, 0, pairOff, pairP, 512);
}

extern "C" void kernel_launch(void* const* d_in, const int* in_sizes, int n_in,
                              void* d_out, int out_size) {
    const float* user_nodes = (const float*)d_in[0];
    const float* food_nodes = (const float*)d_in[1];
    const float* user_W_h = (const float*)d_in[2];
    const float* user_a_h = (const float*)d_in[3];
    const float* user_W_o = (const float*)d_in[4];
    const float* user_a_o = (const float*)d_in[5];
    const float* food_W_h = (const float*)d_in[6];
    const float* food_a_h = (const float*)d_in[7];
    const float* food_W_o = (const float*)d_in[8];
    const float* food_a_o = (const float*)d_in[9];
    const float* mlp_W0 = (const float*)d_in[10];
    const float* mlp_b0 = (const float*)d_in[11];
    const float* mlp_W1 = (const float*)d_in[12];
    const float* mlp_b1 = (const float*)d_in[13];
    const float* mlp_W2 = (const float*)d_in[14];
    const float* mlp_b2 = (const float*)d_in[15];
    const float* mlp_W3 = (const float*)d_in[16];
    const float* mlp_b3 = (const float*)d_in[17];

    static cudaStream_t s_food = nullptr;
    static cudaEvent_t ev_fork = nullptr, ev_join = nullptr;
    if (!s_food) {
        cudaStreamCreateWithFlags(&s_food, cudaStreamNonBlocking);
        cudaEventCreateWithFlags(&ev_fork, cudaEventDisableTiming);
        cudaEventCreateWithFlags(&ev_join, cudaEventDisableTiming);
        cudaFuncSetAttribute(mma_gemm, cudaFuncAttributeMaxDynamicSharedMemorySize,
                             MMA_SMEM_BYTES);
    }

    float* Xn;  GETSYM(Xn, g_Xn);
    float* m3;  GETSYM(m3, g_m3);
    __nv_bfloat16 *pairP, *m1P, *m2P;
    GETSYM(pairP, g_pairP); GETSYM(m1P, g_m1P); GETSYM(m2P, g_m2P);

    Branch br[2];
    for (int b = 0; b < 2; b++) {
        void* t;
        cudaGetSymbolAddress(&t, g_sq);     br[b].sq  = (float*)t + (size_t)b * NNODES;
        cudaGetSymbolAddress(&t, g_sim);    br[b].sim = (float*)t + (size_t)b * NNODES * NNODES;
        cudaGetSymbolAddress(&t, g_Ap);     br[b].Ap  = (__nv_bfloat16*)t + (size_t)b * NNODES * 3 * 1024;
        cudaGetSymbolAddress(&t, g_Bp);     br[b].Bp  = (__nv_bfloat16*)t + (size_t)b * NNODES * 3 * DIM;
        cudaGetSymbolAddress(&t, g_Wp);     br[b].Wp  = (__nv_bfloat16*)t + (size_t)b * 1024 * 3 * 1024;
        cudaGetSymbolAddress(&t, g_bits);   br[b].bits = (unsigned*)t + (size_t)b * NNODES * 64;
        cudaGetSymbolAddress(&t, g_nbr);    br[b].nbr = (int*)t + (size_t)b * NNODES * MAXD;
        cudaGetSymbolAddress(&t, g_cnt);    br[b].cnt = (int*)t + (size_t)b * NNODES;
        cudaGetSymbolAddress(&t, g_Wh);     br[b].Wh  = (float*)t + (size_t)b * NNODES * NHEAD * HIDD;
        cudaGetSymbolAddress(&t, g_s1);     br[b].s1  = (float*)t + (size_t)b * NHEAD * NNODES;
        cudaGetSymbolAddress(&t, g_s2);     br[b].s2  = (float*)t + (size_t)b * NHEAD * NNODES;
        cudaGetSymbolAddress(&t, g_WhO);    br[b].WhO = (float*)t + (size_t)b * NNODES * HIDD;
        cudaGetSymbolAddress(&t, g_sO1);    br[b].sO1 = (float*)t + (size_t)b * NNODES;
        cudaGetSymbolAddress(&t, g_sO2);    br[b].sO2 = (float*)t + (size_t)b * NNODES;
    }

    // fork: food branch runs on s_food concurrently with user branch on stream 0
    cudaEventRecord(ev_fork, 0);
    cudaStreamWaitEvent(s_food, ev_fork, 0);

    run_gat(0, br[0], user_nodes, nullptr, 0, user_W_h, user_a_h, user_W_o, user_a_o, pairP, 0);
    run_gat(s_food, br[1], food_nodes, Xn, 1, food_W_h, food_a_h, food_W_o, food_a_o, pairP, HIDD);

    // join
    cudaEventRecord(ev_join, s_food);
    cudaStreamWaitEvent(0, ev_join, 0);

    // MLP: 512 -> 512 -> 256 -> 128 -> 1 (activations stay packed end-to-end)
    packWgen3_kernel<<<(512 * 512 + 255) / 256, 256>>>(mlp_W0, br[0].Wp, 512, 512);
    launch_mma(0, pairP, br[0].Wp, nullptr, NNODES, 512, 3 * 512, mlp_b0, 1, m1P);

    packWgen3_kernel<<<(512 * 256 + 255) / 256, 256>>>(mlp_W1, br[0].Wp, 512, 256);
    launch_mma(0, m1P, br[0].Wp, nullptr, NNODES, 256, 3 * 512, mlp_b1, 1, m2P);

    packWgen3_kernel<<<(256 * 128 + 255) / 256, 256>>>(mlp_W2, br[0].Wp, 256, 128);
    launch_mma(0, m2P, br[0].Wp, m3, NNODES, 128, 3 * 256, mlp_b2, 1, nullptr);

    mlp3_kernel<<<NNODES / 4, 128>>>(m3, mlp_W3, mlp_b3, (float*)d_out);

    (void)in_sizes; (void)n_in; (void)out_size;
}